// round 4
// baseline (speedup 1.0000x reference)
#include <cuda_runtime.h>
#include <cuda_bf16.h>
#include <cstdint>

// Problem constants (fixed by the dataset)
#define H    256
#define NMAX 8192
#define EMAX 8192
#define KTOT 512            // concatenated K dim: [xi | xj]

// ---------------- scratch (static __device__ — no allocations) ----------------
__device__ uint32_t      g_bits[(size_t)NMAX * (NMAX / 32)];  // 8 MB packed adjacency
__device__ __nv_bfloat16 g_Xhi[(size_t)NMAX * H];             // 4 MB bf16 hi of x
__device__ __nv_bfloat16 g_Xlo[(size_t)NMAX * H];             // 4 MB bf16 lo of x
__device__ __nv_bfloat16 g_Wthi[(size_t)H * KTOT];            // 256 KB: Wt[n][k] hi
__device__ __nv_bfloat16 g_Wtlo[(size_t)H * KTOT];            // 256 KB
__device__ float         g_t[EMAX];                           // per-edge relu(Z)·vf
__device__ float         g_s2[NMAX];                          // s2[n] = x2[n]·vcn
__device__ float         g_vcn[H];                            // Wcn @ ws
__device__ float         g_vf[H];                             // Wf  @ ws
__device__ float         g_ws2[H];                            // vcn + Wlin @ vcn
__device__ float         g_consts[4];                         // [0]=bcn·ws, [1]=bf·ws+bs, [2]=blin·vcn

// ---------------- helpers ----------------
__device__ __forceinline__ float warp_red(float v) {
#pragma unroll
    for (int o = 16; o; o >>= 1) v += __shfl_xor_sync(0xffffffffu, v, o);
    return v;
}

__device__ __forceinline__ float warp_dot256(const float* __restrict__ row,
                                             const float* __restrict__ vec, int lane) {
    float s = 0.f;
#pragma unroll
    for (int c = 0; c < H; c += 32) s = fmaf(row[c + lane], vec[c + lane], s);
    return warp_red(s);
}

__device__ __forceinline__ void mma16816(float c[4], uint32_t a0, uint32_t a1,
                                         uint32_t a2, uint32_t a3,
                                         uint32_t b0, uint32_t b1) {
    asm volatile(
        "mma.sync.aligned.m16n8k16.row.col.f32.bf16.bf16.f32 "
        "{%0,%1,%2,%3}, {%4,%5,%6,%7}, {%8,%9}, {%0,%1,%2,%3};"
        : "+f"(c[0]), "+f"(c[1]), "+f"(c[2]), "+f"(c[3])
        : "r"(a0), "r"(a1), "r"(a2), "r"(a3), "r"(b0), "r"(b1));
}

// ---------------- prep: split x -> (Xhi, Xlo), build Wt = [Wi;Wj]^T hi/lo ----------------
__global__ void __launch_bounds__(256) prep_kernel(const float* __restrict__ x,
                                                   const float* __restrict__ Wi,
                                                   const float* __restrict__ Wj) {
    int bid = blockIdx.x;
    int tid = threadIdx.x;
    if (bid < (NMAX * H) / 1024) {
        int gid = bid * 256 + tid;
        float4 v = ((const float4*)x)[gid];
        __nv_bfloat16 hx = __float2bfloat16(v.x), hy = __float2bfloat16(v.y);
        __nv_bfloat16 hz = __float2bfloat16(v.z), hw = __float2bfloat16(v.w);
        __nv_bfloat16 lx = __float2bfloat16(v.x - __bfloat162float(hx));
        __nv_bfloat16 ly = __float2bfloat16(v.y - __bfloat162float(hy));
        __nv_bfloat16 lz = __float2bfloat16(v.z - __bfloat162float(hz));
        __nv_bfloat16 lw = __float2bfloat16(v.w - __bfloat162float(hw));
        ((__nv_bfloat162*)g_Xhi)[gid * 2 + 0] = __nv_bfloat162(hx, hy);
        ((__nv_bfloat162*)g_Xhi)[gid * 2 + 1] = __nv_bfloat162(hz, hw);
        ((__nv_bfloat162*)g_Xlo)[gid * 2 + 0] = __nv_bfloat162(lx, ly);
        ((__nv_bfloat162*)g_Xlo)[gid * 2 + 1] = __nv_bfloat162(lz, lw);
    } else {
        int n = bid - (NMAX * H) / 1024;
        if (n >= H) return;
        for (int k = tid; k < KTOT; k += 256) {
            float w = (k < H) ? Wi[(size_t)k * H + n] : Wj[(size_t)(k - H) * H + n];
            __nv_bfloat16 hi = __float2bfloat16(w);
            __nv_bfloat16 lo = __float2bfloat16(w - __bfloat162float(hi));
            g_Wthi[(size_t)n * KTOT + k] = hi;
            g_Wtlo[(size_t)n * KTOT + k] = lo;
        }
    }
}

// ---------------- K0a: vcn = Wcn@ws, vf = Wf@ws ----------------
__global__ void __launch_bounds__(256) k0a_kernel(const float* __restrict__ Wcn,
                                                  const float* __restrict__ Wf,
                                                  const float* __restrict__ ws) {
    int gw = (blockIdx.x * blockDim.x + threadIdx.x) >> 5;
    int lane = threadIdx.x & 31;
    if (gw < H) {
        float d = warp_dot256(Wcn + (size_t)gw * H, ws, lane);
        if (!lane) g_vcn[gw] = d;
    } else if (gw < 2 * H) {
        int r = gw - H;
        float d = warp_dot256(Wf + (size_t)r * H, ws, lane);
        if (!lane) g_vf[r] = d;
    }
}

// ---------------- K0b: ws2 = vcn + Wlin@vcn, scalar constants ----------------
__global__ void __launch_bounds__(256) k0b_kernel(const float* __restrict__ Wlin,
                                                  const float* __restrict__ blin,
                                                  const float* __restrict__ bcn,
                                                  const float* __restrict__ bf,
                                                  const float* __restrict__ ws,
                                                  const float* __restrict__ bs) {
    int gw = (blockIdx.x * blockDim.x + threadIdx.x) >> 5;
    int lane = threadIdx.x & 31;
    if (gw < H) {
        float d = warp_dot256(Wlin + (size_t)gw * H, g_vcn, lane);
        if (!lane) g_ws2[gw] = g_vcn[gw] + d;
    } else if (gw == H) {
        float d = warp_dot256(blin, g_vcn, lane);
        if (!lane) g_consts[2] = d;
    } else if (gw == H + 1) {
        float d = warp_dot256(bcn, ws, lane);
        if (!lane) g_consts[0] = d;
    } else if (gw == H + 2) {
        float d = warp_dot256(bf, ws, lane);
        if (!lane) g_consts[1] = d + bs[0];
    }
}

// ---------------- pack body: one warp packs 1024 adj floats -> 32 bit-words ----------------
// 8-load batches: MLP=8, only ~16 live registers.
__device__ __forceinline__ void pack_warp(const float* __restrict__ adj,
                                          size_t gw, int lane) {
    size_t fbase = gw * 1024;
    uint32_t myword = 0;
#pragma unroll
    for (int r = 0; r < 4; r++) {
        float v[8];
#pragma unroll
        for (int i = 0; i < 8; i++) v[i] = adj[fbase + (size_t)(r * 8 + i) * 32 + lane];
#pragma unroll
        for (int i = 0; i < 8; i++) {
            uint32_t b = __ballot_sync(0xffffffffu, v[i] != 0.0f);
            if (lane == (r * 8 + i)) myword = b;
        }
    }
    g_bits[gw * 32 + lane] = myword;
}

// ---------------- tensor-core edge GEMM body (register-lean) ----------------
// 64 edges x 256 cols, K=512, split-bf16 3-pass. Columns processed in TWO
// 128-wide passes reusing acc[8][4] (epilogue is a column-sum, so partials add).
#define ROWPAD 12
__device__ __forceinline__ void gemm_block(int gb, const int* __restrict__ tei, int E,
                                           const float* __restrict__ bi,
                                           const float* __restrict__ bj,
                                           uint32_t* smem) {
    uint32_t* AsHi = smem;                   // 64*12
    uint32_t* AsLo = smem + 768;             // 64*12
    uint32_t* BsHi = smem + 1536;            // 128*12
    uint32_t* BsLo = smem + 3072;            // 128*12
    float*    tsum = (float*)(smem + 4608);  // [2][64]
    int*      eidx = (int*)(smem + 4736);    // [64 src][64 dst]

    int tid = threadIdx.x;
    int lane = tid & 31, wid = tid >> 5;
    int wm = wid & 3, wn = wid >> 2;         // 4 m-groups x 2 n-groups (per 128-col half)
    int ebase = gb * 64;

    if (tid < 64) {
        eidx[tid]      = tei[ebase + tid];
        eidx[64 + tid] = tei[E + ebase + tid];
    }
    __syncthreads();

    int arow = tid >> 2;                     // A-load row per thread
    int aq   = tid & 3;                      // A-load quad (4 bf16)
    int brow = tid >> 1;                     // B-load row (n) per thread
    int bhalf = tid & 1;                     // B-load k-half (8 bf16)
    int r0 = wm * 16 + (lane >> 2);
    int w4 = lane & 3;

    float tp0 = 0.f, tp1 = 0.f;

#pragma unroll
    for (int np = 0; np < 2; np++) {
        float acc[8][4];
#pragma unroll
        for (int j = 0; j < 8; j++)
#pragma unroll
            for (int q = 0; q < 4; q++) acc[j][q] = 0.f;

        for (int ks = 0; ks < KTOT / 16; ks++) {
            int k0 = ks * 16;
            // A tile (64 x 16, hi+lo) gathered by edge endpoint
            {
                int node = eidx[(k0 < H ? 0 : 64) + arow];
                int gc = (k0 & (H - 1)) + aq * 4;
                uint2 vh = *(const uint2*)(g_Xhi + (size_t)node * H + gc);
                uint2 vl = *(const uint2*)(g_Xlo + (size_t)node * H + gc);
                AsHi[arow * ROWPAD + aq * 2 + 0] = vh.x;
                AsHi[arow * ROWPAD + aq * 2 + 1] = vh.y;
                AsLo[arow * ROWPAD + aq * 2 + 0] = vl.x;
                AsLo[arow * ROWPAD + aq * 2 + 1] = vl.y;
            }
            // B tile (128 n-rows x 16 k, hi+lo): each thread one 8-bf16 half-row
            {
                size_t goff = (size_t)(np * 128 + brow) * KTOT + k0 + bhalf * 8;
                *(uint4*)&BsHi[brow * ROWPAD + bhalf * 4] = *(const uint4*)(g_Wthi + goff);
                *(uint4*)&BsLo[brow * ROWPAD + bhalf * 4] = *(const uint4*)(g_Wtlo + goff);
            }
            __syncthreads();

            uint32_t ah0 = AsHi[r0 * ROWPAD + w4];
            uint32_t ah1 = AsHi[(r0 + 8) * ROWPAD + w4];
            uint32_t ah2 = AsHi[r0 * ROWPAD + w4 + 4];
            uint32_t ah3 = AsHi[(r0 + 8) * ROWPAD + w4 + 4];
            uint32_t al0 = AsLo[r0 * ROWPAD + w4];
            uint32_t al1 = AsLo[(r0 + 8) * ROWPAD + w4];
            uint32_t al2 = AsLo[r0 * ROWPAD + w4 + 4];
            uint32_t al3 = AsLo[(r0 + 8) * ROWPAD + w4 + 4];

#pragma unroll
            for (int j = 0; j < 8; j++) {
                int nr = wn * 64 + j * 8 + (lane >> 2);
                uint32_t bh0 = BsHi[nr * ROWPAD + w4];
                uint32_t bh1 = BsHi[nr * ROWPAD + w4 + 4];
                uint32_t bl0 = BsLo[nr * ROWPAD + w4];
                uint32_t bl1 = BsLo[nr * ROWPAD + w4 + 4];
                mma16816(acc[j], ah0, ah1, ah2, ah3, bh0, bh1);   // hi*hi
                mma16816(acc[j], ah0, ah1, ah2, ah3, bl0, bl1);   // hi*lo
                mma16816(acc[j], al0, al1, al2, al3, bh0, bh1);   // lo*hi
            }
            __syncthreads();
        }

        // epilogue for this 128-col half: accumulate t partials
#pragma unroll
        for (int j = 0; j < 8; j++) {
            int col = np * 128 + wn * 64 + j * 8 + (lane & 3) * 2;
            float b0 = bi[col] + bj[col];
            float b1 = bi[col + 1] + bj[col + 1];
            float v0 = g_vf[col], v1 = g_vf[col + 1];
            tp0 += fmaxf(acc[j][0] + b0, 0.f) * v0 + fmaxf(acc[j][1] + b1, 0.f) * v1;
            tp1 += fmaxf(acc[j][2] + b0, 0.f) * v0 + fmaxf(acc[j][3] + b1, 0.f) * v1;
        }
    }

    tp0 += __shfl_xor_sync(0xffffffffu, tp0, 1);
    tp0 += __shfl_xor_sync(0xffffffffu, tp0, 2);
    tp1 += __shfl_xor_sync(0xffffffffu, tp1, 1);
    tp1 += __shfl_xor_sync(0xffffffffu, tp1, 2);
    if ((lane & 3) == 0) {
        int r = wm * 16 + (lane >> 2);
        tsum[wn * 64 + r] = tp0;
        tsum[wn * 64 + r + 8] = tp1;
    }
    __syncthreads();
    if (tid < 64) g_t[ebase + tid] = tsum[tid] + tsum[64 + tid];
}

// ---------------- fused kernel: pack ∪ tensor-GEMM ∪ s2 ----------------
// __launch_bounds__(256, 4): cap regs at 64 so the DRAM-bound pack role gets
// 4 blocks/SM (32 warps) instead of 2 (the R3 occupancy bug).
__global__ void __launch_bounds__(256, 4) fused_kernel(const float* __restrict__ x,
                                                       const float* __restrict__ adj,
                                                       const int* __restrict__ tei,
                                                       const float* __restrict__ bi,
                                                       const float* __restrict__ bj,
                                                       int N, int E) {
    __shared__ uint32_t smem[4864];   // 19 KB (gemm role only)

    const int nbGemm = E / 64;        // 128
    const int nbS2   = N / 8;         // 1024
    int bid = blockIdx.x;
    int warp = threadIdx.x >> 5;
    int lane = threadIdx.x & 31;

    if (bid < 2 * nbGemm) {
        int half = bid >> 1;
        if ((bid & 1) == 0) {
            gemm_block(half, tei, E, bi, bj, smem);
        } else {
            pack_warp(adj, (size_t)half * 8 + warp, lane);
        }
    } else if (bid < 2 * nbGemm + nbS2) {
        int node = (bid - 2 * nbGemm) * 8 + warp;
        if (node < N) {
            float d = warp_dot256(x + (size_t)node * H, g_ws2, lane);
            if (!lane) g_s2[node] = d + g_consts[2];
        }
    } else {
        int pb = nbGemm + (bid - 2 * nbGemm - nbS2);
        pack_warp(adj, (size_t)pb * 8 + warp, lane);
    }
}

// ---------------- final edge kernel: CN bit-AND gather + combine + softplus ----------------
__global__ void __launch_bounds__(256) edge_kernel(const int* __restrict__ tei, int E, int nwords,
                                                   const float* __restrict__ beta_p,
                                                   const int* __restrict__ boolen_p,
                                                   float* __restrict__ out) {
    int gw = (blockIdx.x * blockDim.x + threadIdx.x) >> 5;
    int lane = threadIdx.x & 31;
    if (gw >= E) return;

    int src = tei[gw];
    int dst = tei[E + gw];

    const uint32_t* bsrc = g_bits + (size_t)src * nwords;
    const uint32_t* bdst = g_bits + (size_t)dst * nwords;

    float s = 0.f;
    int rounds = nwords >> 5;          // 8 for N=8192
    for (int rb = 0; rb < rounds; rb += 8) {
        uint32_t aw[8], bw[8];
#pragma unroll
        for (int i = 0; i < 8; i++) {
            int w = lane + ((rb + i) << 5);
            aw[i] = bsrc[w];
            bw[i] = bdst[w];
        }
#pragma unroll
        for (int i = 0; i < 8; i++) {
            int w = lane + ((rb + i) << 5);
            uint32_t a = aw[i] & bw[i];
            while (a) {
                int b = __ffs(a) - 1;
                a &= a - 1;
                s += g_s2[(w << 5) + b];
            }
        }
    }
    float S = warp_red(s);

    if (!lane) {
        float beta = beta_p[0];
        float u = g_t[gw] + beta * (S + g_consts[0]) + g_consts[1];
        bool pos = boolen_p ? (boolen_p[0] != 0) : true;
        float v = pos ? u : -u;
        out[gw] = fmaxf(-v, 0.f) + log1pf(expf(-fabsf(v)));  // softplus(-v)
    }
}

// ---------------- launch ----------------
extern "C" void kernel_launch(void* const* d_in, const int* in_sizes, int n_in,
                              void* d_out, int out_size) {
    const float* x    = (const float*)d_in[0];
    const float* adj  = (const float*)d_in[1];
    const int*   tei  = (const int*)d_in[2];
    const float* Wlin = (const float*)d_in[3];
    const float* blin = (const float*)d_in[4];
    const float* Wcn  = (const float*)d_in[5];
    const float* bcn  = (const float*)d_in[6];
    const float* Wi   = (const float*)d_in[7];
    const float* bi   = (const float*)d_in[8];
    const float* Wj   = (const float*)d_in[9];
    const float* bj   = (const float*)d_in[10];
    const float* Wf   = (const float*)d_in[11];
    const float* bf   = (const float*)d_in[12];
    const float* ws   = (const float*)d_in[13];
    const float* bs   = (const float*)d_in[14];
    const float* beta = (const float*)d_in[15];
    const int* boolen = (n_in > 16) ? (const int*)d_in[16] : nullptr;
    float* out = (float*)d_out;

    const int N = in_sizes[0] / H;   // 8192 nodes
    const int E = in_sizes[2] / 2;   // 8192 edges
    const int nwords = N / 32;       // 256 words per adjacency row

    prep_kernel<<<(NMAX * H) / 1024 + H, 256>>>(x, Wi, Wj);
    k0a_kernel<<<(2 * H + 7) / 8, 256>>>(Wcn, Wf, ws);
    k0b_kernel<<<(H + 3 + 7) / 8, 256>>>(Wlin, blin, bcn, bf, ws, bs);
    {
        int nbGemm = E / 64;                              // 128
        int nbS2   = N / 8;                               // 1024
        int nbPack = (int)((long long)N * N / 1024 / 8);  // 8192
        int total = nbGemm + nbS2 + nbPack;               // 9344
        fused_kernel<<<total, 256>>>(x, adj, tei, bi, bj, N, E);
    }
    edge_kernel<<<(E + 7) / 8, 256>>>(tei, E, nwords, beta, boolen, out);
}

// round 5
// speedup vs baseline: 1.8357x; 1.8357x over previous
#include <cuda_runtime.h>
#include <cuda_bf16.h>
#include <cstdint>

// Problem constants (fixed by the dataset)
#define H    256
#define NMAX 8192
#define EMAX 8192
#define KTOT 512            // concatenated K dim: [xi | xj]

// ---------------- scratch (static __device__ — no allocations) ----------------
__device__ uint32_t      g_bits[(size_t)NMAX * (NMAX / 32)];  // 8 MB packed adjacency
__device__ __nv_bfloat16 g_Xhi[(size_t)NMAX * H];             // 4 MB bf16 hi of x
__device__ __nv_bfloat16 g_Xlo[(size_t)NMAX * H];             // 4 MB bf16 lo of x
__device__ __nv_bfloat16 g_Wthi[(size_t)H * KTOT];            // 256 KB: Wt[n][k] hi
__device__ __nv_bfloat16 g_Wtlo[(size_t)H * KTOT];            // 256 KB
__device__ float         g_t0[EMAX];                          // per-edge relu-dot, cols 0-127
__device__ float         g_t1[EMAX];                          // per-edge relu-dot, cols 128-255
__device__ float         g_s2[NMAX];                          // s2[n] = x2[n]·vcn
__device__ float         g_vcn[H];
__device__ float         g_vf[H];
__device__ float         g_ws2[H];
__device__ float         g_consts[4];                         // [0]=bcn·ws, [1]=bf·ws+bs, [2]=blin·vcn
__device__ unsigned char g_flag[NMAX];                        // adj row referenced by any edge?

// ---------------- helpers ----------------
__device__ __forceinline__ float warp_red(float v) {
#pragma unroll
    for (int o = 16; o; o >>= 1) v += __shfl_xor_sync(0xffffffffu, v, o);
    return v;
}

__device__ __forceinline__ float warp_dot256(const float* __restrict__ row,
                                             const float* __restrict__ vec, int lane) {
    float s = 0.f;
#pragma unroll
    for (int c = 0; c < H; c += 32) s = fmaf(row[c + lane], vec[c + lane], s);
    return warp_red(s);
}

__device__ __forceinline__ void mma16816(float c[4], const uint32_t a[4],
                                         uint32_t b0, uint32_t b1) {
    asm volatile(
        "mma.sync.aligned.m16n8k16.row.col.f32.bf16.bf16.f32 "
        "{%0,%1,%2,%3}, {%4,%5,%6,%7}, {%8,%9}, {%0,%1,%2,%3};"
        : "+f"(c[0]), "+f"(c[1]), "+f"(c[2]), "+f"(c[3])
        : "r"(a[0]), "r"(a[1]), "r"(a[2]), "r"(a[3]), "r"(b0), "r"(b1));
}

__device__ __forceinline__ void ldsm4(uint32_t r[4], uint32_t addr) {
    asm volatile("ldmatrix.sync.aligned.m8n8.x4.shared.b16 {%0,%1,%2,%3}, [%4];"
        : "=r"(r[0]), "=r"(r[1]), "=r"(r[2]), "=r"(r[3]) : "r"(addr));
}

// ---------------- prep: split x, build Wt hi/lo, zero flags ----------------
__global__ void __launch_bounds__(256) prep_kernel(const float* __restrict__ x,
                                                   const float* __restrict__ Wi,
                                                   const float* __restrict__ Wj) {
    int bid = blockIdx.x;
    int tid = threadIdx.x;
    const int XB = (NMAX * H) / 1024;          // 2048
    if (bid < XB) {
        int gid = bid * 256 + tid;
        float4 v = ((const float4*)x)[gid];
        __nv_bfloat16 hx = __float2bfloat16(v.x), hy = __float2bfloat16(v.y);
        __nv_bfloat16 hz = __float2bfloat16(v.z), hw = __float2bfloat16(v.w);
        __nv_bfloat16 lx = __float2bfloat16(v.x - __bfloat162float(hx));
        __nv_bfloat16 ly = __float2bfloat16(v.y - __bfloat162float(hy));
        __nv_bfloat16 lz = __float2bfloat16(v.z - __bfloat162float(hz));
        __nv_bfloat16 lw = __float2bfloat16(v.w - __bfloat162float(hw));
        ((__nv_bfloat162*)g_Xhi)[gid * 2 + 0] = __nv_bfloat162(hx, hy);
        ((__nv_bfloat162*)g_Xhi)[gid * 2 + 1] = __nv_bfloat162(hz, hw);
        ((__nv_bfloat162*)g_Xlo)[gid * 2 + 0] = __nv_bfloat162(lx, ly);
        ((__nv_bfloat162*)g_Xlo)[gid * 2 + 1] = __nv_bfloat162(lz, lw);
    } else if (bid < XB + H) {
        int n = bid - XB;
        for (int k = tid; k < KTOT; k += 256) {
            float w = (k < H) ? Wi[(size_t)k * H + n] : Wj[(size_t)(k - H) * H + n];
            __nv_bfloat16 hi = __float2bfloat16(w);
            __nv_bfloat16 lo = __float2bfloat16(w - __bfloat162float(hi));
            g_Wthi[(size_t)n * KTOT + k] = hi;
            g_Wtlo[(size_t)n * KTOT + k] = lo;
        }
    } else {
        int idx = (bid - XB - H) * 256 + tid;
        if (idx < NMAX) g_flag[idx] = 0;
    }
}

// ---------------- flagset: mark adj rows referenced by edges ----------------
__global__ void __launch_bounds__(256) flagset_kernel(const int* __restrict__ tei, int twoE) {
    int gid = blockIdx.x * 256 + threadIdx.x;
    if (gid < twoE) g_flag[tei[gid]] = 1;
}

// ---------------- K0a / K0b: fold the 1-wide head ----------------
__global__ void __launch_bounds__(256) k0a_kernel(const float* __restrict__ Wcn,
                                                  const float* __restrict__ Wf,
                                                  const float* __restrict__ ws) {
    int gw = (blockIdx.x * blockDim.x + threadIdx.x) >> 5;
    int lane = threadIdx.x & 31;
    if (gw < H) {
        float d = warp_dot256(Wcn + (size_t)gw * H, ws, lane);
        if (!lane) g_vcn[gw] = d;
    } else if (gw < 2 * H) {
        int r = gw - H;
        float d = warp_dot256(Wf + (size_t)r * H, ws, lane);
        if (!lane) g_vf[r] = d;
    }
}

__global__ void __launch_bounds__(256) k0b_kernel(const float* __restrict__ Wlin,
                                                  const float* __restrict__ blin,
                                                  const float* __restrict__ bcn,
                                                  const float* __restrict__ bf,
                                                  const float* __restrict__ ws,
                                                  const float* __restrict__ bs) {
    int gw = (blockIdx.x * blockDim.x + threadIdx.x) >> 5;
    int lane = threadIdx.x & 31;
    if (gw < H) {
        float d = warp_dot256(Wlin + (size_t)gw * H, g_vcn, lane);
        if (!lane) g_ws2[gw] = g_vcn[gw] + d;
    } else if (gw == H) {
        float d = warp_dot256(blin, g_vcn, lane);
        if (!lane) g_consts[2] = d;
    } else if (gw == H + 1) {
        float d = warp_dot256(bcn, ws, lane);
        if (!lane) g_consts[0] = d;
    } else if (gw == H + 2) {
        float d = warp_dot256(bf, ws, lane);
        if (!lane) g_consts[1] = d + bs[0];
    }
}

// ---------------- pack: one warp packs 2048 adj floats via LDG.128 ----------------
// 8 front-batched float4 streaming loads (32 lines in flight), nibble build +
// 3 shfl-ORs per 128-float chunk replace the ballot chain.
__device__ __forceinline__ void pack_warp(const float* __restrict__ adj,
                                          size_t gw, int lane) {
    if (!g_flag[gw >> 2]) return;                 // adj row never referenced
    size_t fbase = gw * 2048;
    int grp = lane >> 3;                          // 4 groups of 8 lanes
    int sh  = (lane & 7) * 4;
#pragma unroll
    for (int r = 0; r < 2; r++) {
        float4 v[8];
#pragma unroll
        for (int i = 0; i < 8; i++)
            v[i] = __ldcs(((const float4*)(adj + fbase + (size_t)(r * 8 + i) * 128)) + lane);
#pragma unroll
        for (int i = 0; i < 8; i++) {
            uint32_t nib = (uint32_t)(v[i].x != 0.f)
                         | ((uint32_t)(v[i].y != 0.f) << 1)
                         | ((uint32_t)(v[i].z != 0.f) << 2)
                         | ((uint32_t)(v[i].w != 0.f) << 3);
            uint32_t w = nib << sh;
            w |= __shfl_xor_sync(0xffffffffu, w, 1);
            w |= __shfl_xor_sync(0xffffffffu, w, 2);
            w |= __shfl_xor_sync(0xffffffffu, w, 4);
            if ((lane & 7) == 0)
                g_bits[gw * 64 + (size_t)(r * 8 + i) * 4 + grp] = w;
        }
    }
}

// ---------------- tensor-core edge GEMM body: 64 edges x 128 cols, K=512 ----------------
// split-bf16 3-pass (hi*hi + hi*lo + lo*hi), ldmatrix fragments, acc[8][4]=32 regs.
#define ROWPAD 12
__device__ __forceinline__ void gemm_block(int h, const int* __restrict__ tei, int E,
                                           const float* __restrict__ bi,
                                           const float* __restrict__ bj,
                                           uint32_t* smem) {
    uint32_t* AsHi = smem;                   // 64*12
    uint32_t* AsLo = smem + 768;
    uint32_t* BsHi = smem + 1536;            // 128*12
    uint32_t* BsLo = smem + 3072;
    float*    tsum = (float*)(smem + 4608);  // [2][64]
    int*      eidx = (int*)(smem + 4736);    // [64 src][64 dst]

    int np = h & 1;                          // column half: 0 -> cols 0-127, 1 -> 128-255
    int eb = h >> 1;                         // edge tile
    int ebase = eb * 64;

    int tid = threadIdx.x;
    int lane = tid & 31, wid = tid >> 5;
    int wm = wid & 3, wn = wid >> 2;         // 4 m-groups x 2 n-groups

    if (tid < 64) {
        eidx[tid]      = tei[ebase + tid];
        eidx[64 + tid] = tei[E + ebase + tid];
    }
    __syncthreads();

    int arow = tid >> 2, aq = tid & 3;       // A smem-fill mapping
    int brow = tid >> 1, bh2 = tid & 1;      // B smem-fill mapping

    // ldmatrix lane addressing (constant over k-steps)
    uint32_t asHiB = (uint32_t)__cvta_generic_to_shared(AsHi);
    uint32_t asLoB = (uint32_t)__cvta_generic_to_shared(AsLo);
    uint32_t bsHiB = (uint32_t)__cvta_generic_to_shared(BsHi);
    uint32_t bsLoB = (uint32_t)__cvta_generic_to_shared(BsLo);
    uint32_t aoff = (uint32_t)((wm * 16 + (lane & 15)) * 48 + (lane >> 4) * 16);
    uint32_t boff[4];
#pragma unroll
    for (int jj = 0; jj < 4; jj++)
        boff[jj] = (uint32_t)((wn * 64 + jj * 16 + (lane & 15)) * 48 + (lane >> 4) * 16);

    float acc[8][4];
#pragma unroll
    for (int j = 0; j < 8; j++)
#pragma unroll
        for (int q = 0; q < 4; q++) acc[j][q] = 0.f;

    for (int ks = 0; ks < KTOT / 16; ks++) {
        int k0 = ks * 16;
        // fill A tile (64 x 16 hi+lo), gathered by edge endpoint
        {
            int node = eidx[(k0 < H ? 0 : 64) + arow];
            int gc = (k0 & (H - 1)) + aq * 4;
            uint2 vh = *(const uint2*)(g_Xhi + (size_t)node * H + gc);
            uint2 vl = *(const uint2*)(g_Xlo + (size_t)node * H + gc);
            AsHi[arow * ROWPAD + aq * 2 + 0] = vh.x;
            AsHi[arow * ROWPAD + aq * 2 + 1] = vh.y;
            AsLo[arow * ROWPAD + aq * 2 + 0] = vl.x;
            AsLo[arow * ROWPAD + aq * 2 + 1] = vl.y;
        }
        // fill B tile (128 n-rows x 16 k hi+lo)
        {
            size_t goff = (size_t)(np * 128 + brow) * KTOT + k0 + bh2 * 8;
            *(uint4*)&BsHi[brow * ROWPAD + bh2 * 4] = *(const uint4*)(g_Wthi + goff);
            *(uint4*)&BsLo[brow * ROWPAD + bh2 * 4] = *(const uint4*)(g_Wtlo + goff);
        }
        __syncthreads();

        uint32_t ah[4], al[4];
        ldsm4(ah, asHiB + aoff);
        ldsm4(al, asLoB + aoff);
#pragma unroll
        for (int jj = 0; jj < 4; jj++) {
            uint32_t bhf[4], blf[4];
            ldsm4(bhf, bsHiB + boff[jj]);
            ldsm4(blf, bsLoB + boff[jj]);
            mma16816(acc[2 * jj],     ah, bhf[0], bhf[2]);   // hi*hi (even j)
            mma16816(acc[2 * jj],     ah, blf[0], blf[2]);   // hi*lo
            mma16816(acc[2 * jj],     al, bhf[0], bhf[2]);   // lo*hi
            mma16816(acc[2 * jj + 1], ah, bhf[1], bhf[3]);
            mma16816(acc[2 * jj + 1], ah, blf[1], blf[3]);
            mma16816(acc[2 * jj + 1], al, bhf[1], bhf[3]);
        }
        __syncthreads();
    }

    // epilogue: t-partials = sum over this block's 128 cols of relu(z+b)*vf
    float tp0 = 0.f, tp1 = 0.f;
#pragma unroll
    for (int j = 0; j < 8; j++) {
        int col = np * 128 + wn * 64 + j * 8 + (lane & 3) * 2;
        float b0 = bi[col] + bj[col];
        float b1 = bi[col + 1] + bj[col + 1];
        float v0 = g_vf[col], v1 = g_vf[col + 1];
        tp0 += fmaxf(acc[j][0] + b0, 0.f) * v0 + fmaxf(acc[j][1] + b1, 0.f) * v1;
        tp1 += fmaxf(acc[j][2] + b0, 0.f) * v0 + fmaxf(acc[j][3] + b1, 0.f) * v1;
    }
    tp0 += __shfl_xor_sync(0xffffffffu, tp0, 1);
    tp0 += __shfl_xor_sync(0xffffffffu, tp0, 2);
    tp1 += __shfl_xor_sync(0xffffffffu, tp1, 1);
    tp1 += __shfl_xor_sync(0xffffffffu, tp1, 2);
    if ((lane & 3) == 0) {
        int r = wm * 16 + (lane >> 2);
        tsum[wn * 64 + r] = tp0;
        tsum[wn * 64 + r + 8] = tp1;
    }
    __syncthreads();
    if (tid < 64) {
        float v = tsum[tid] + tsum[64 + tid];
        if (np == 0) g_t0[ebase + tid] = v;
        else         g_t1[ebase + tid] = v;
    }
}

// ---------------- fused kernel: pack ∪ tensor-GEMM ∪ s2 ----------------
__global__ void __launch_bounds__(256, 3) fused_kernel(const float* __restrict__ x,
                                                       const float* __restrict__ adj,
                                                       const int* __restrict__ tei,
                                                       const float* __restrict__ bi,
                                                       const float* __restrict__ bj,
                                                       int N, int E) {
    __shared__ uint32_t smem[4864];   // 19 KB (gemm role only)

    const int nbGemm = (E / 64) * 2;  // 256
    const int nbS2   = N / 8;         // 1024
    int bid = blockIdx.x;
    int warp = threadIdx.x >> 5;
    int lane = threadIdx.x & 31;

    if (bid < 2 * nbGemm) {
        int half = bid >> 1;
        if ((bid & 1) == 0) {
            gemm_block(half, tei, E, bi, bj, smem);
        } else {
            pack_warp(adj, (size_t)half * 8 + warp, lane);
        }
    } else if (bid < 2 * nbGemm + nbS2) {
        int node = (bid - 2 * nbGemm) * 8 + warp;
        if (node < N) {
            float d = warp_dot256(x + (size_t)node * H, g_ws2, lane);
            if (!lane) g_s2[node] = d + g_consts[2];
        }
    } else {
        int pb = nbGemm + (bid - 2 * nbGemm - nbS2);
        pack_warp(adj, (size_t)pb * 8 + warp, lane);
    }
}

// ---------------- final edge kernel ----------------
__global__ void __launch_bounds__(256) edge_kernel(const int* __restrict__ tei, int E, int nwords,
                                                   const float* __restrict__ beta_p,
                                                   const int* __restrict__ boolen_p,
                                                   float* __restrict__ out) {
    int gw = (blockIdx.x * blockDim.x + threadIdx.x) >> 5;
    int lane = threadIdx.x & 31;
    if (gw >= E) return;

    int src = tei[gw];
    int dst = tei[E + gw];

    const uint32_t* bsrc = g_bits + (size_t)src * nwords;
    const uint32_t* bdst = g_bits + (size_t)dst * nwords;

    float s = 0.f;
    int rounds = nwords >> 5;          // 8 for N=8192
    for (int rb = 0; rb < rounds; rb += 8) {
        uint32_t aw[8], bw[8];
#pragma unroll
        for (int i = 0; i < 8; i++) {
            int w = lane + ((rb + i) << 5);
            aw[i] = bsrc[w];
            bw[i] = bdst[w];
        }
#pragma unroll
        for (int i = 0; i < 8; i++) {
            int w = lane + ((rb + i) << 5);
            uint32_t a = aw[i] & bw[i];
            while (a) {
                int b = __ffs(a) - 1;
                a &= a - 1;
                s += g_s2[(w << 5) + b];
            }
        }
    }
    float S = warp_red(s);

    if (!lane) {
        float beta = beta_p[0];
        float u = g_t0[gw] + g_t1[gw] + beta * (S + g_consts[0]) + g_consts[1];
        bool pos = boolen_p ? (boolen_p[0] != 0) : true;
        float v = pos ? u : -u;
        out[gw] = fmaxf(-v, 0.f) + log1pf(expf(-fabsf(v)));  // softplus(-v)
    }
}

// ---------------- launch ----------------
extern "C" void kernel_launch(void* const* d_in, const int* in_sizes, int n_in,
                              void* d_out, int out_size) {
    const float* x    = (const float*)d_in[0];
    const float* adj  = (const float*)d_in[1];
    const int*   tei  = (const int*)d_in[2];
    const float* Wlin = (const float*)d_in[3];
    const float* blin = (const float*)d_in[4];
    const float* Wcn  = (const float*)d_in[5];
    const float* bcn  = (const float*)d_in[6];
    const float* Wi   = (const float*)d_in[7];
    const float* bi   = (const float*)d_in[8];
    const float* Wj   = (const float*)d_in[9];
    const float* bj   = (const float*)d_in[10];
    const float* Wf   = (const float*)d_in[11];
    const float* bf   = (const float*)d_in[12];
    const float* ws   = (const float*)d_in[13];
    const float* bs   = (const float*)d_in[14];
    const float* beta = (const float*)d_in[15];
    const int* boolen = (n_in > 16) ? (const int*)d_in[16] : nullptr;
    float* out = (float*)d_out;

    const int N = in_sizes[0] / H;   // 8192 nodes
    const int E = in_sizes[2] / 2;   // 8192 edges
    const int nwords = N / 32;       // 256 words per adjacency row

    // 1) prep (x/W split + flag zero), then edge-endpoint flags
    prep_kernel<<<(NMAX * H) / 1024 + H + (NMAX + 255) / 256, 256>>>(x, Wi, Wj);
    flagset_kernel<<<(2 * E + 255) / 256, 256>>>(tei, 2 * E);
    // 2) fold the 1-wide head
    k0a_kernel<<<(2 * H + 7) / 8, 256>>>(Wcn, Wf, ws);
    k0b_kernel<<<(H + 3 + 7) / 8, 256>>>(Wlin, blin, bcn, bf, ws, bs);
    // 3) fused: pack (DRAM) + tensor GEMM + s2 GEMV
    {
        int nbGemm = (E / 64) * 2;                        // 256
        int nbS2   = N / 8;                               // 1024
        int nbPack = (int)((long long)N * N / 2048 / 8);  // 4096
        int total = nbGemm + nbS2 + nbPack;               // 5376
        fused_kernel<<<total, 256>>>(x, adj, tei, bi, bj, N, E);
    }
    // 4) per-edge: CN bit-AND gather + combine + softplus
    edge_kernel<<<(E + 7) / 8, 256>>>(tei, E, nwords, beta, boolen, out);
}